// round 14
// baseline (speedup 1.0000x reference)
#include <cuda_runtime.h>

#define NQ       10
#define DIM      1024
#define NLAYERS  4
#define NT       64           // 64 threads = 2 warps = one state-pair (2 batch elems)
#define PI_F     3.14159265358979323846f

typedef unsigned long long u64;

// ---- packed f32x2 helpers (batch0 in lo, batch1 in hi) ----
__device__ __forceinline__ u64 pk2(float lo, float hi) {
    u64 r; asm("mov.b64 %0, {%1, %2};" : "=l"(r) : "f"(lo), "f"(hi)); return r;
}
__device__ __forceinline__ void upk2(u64 v, float& lo, float& hi) {
    asm("mov.b64 {%0, %1}, %2;" : "=f"(lo), "=f"(hi) : "l"(v));
}
__device__ __forceinline__ u64 fma2(u64 a, u64 b, u64 c) {
    u64 d; asm("fma.rn.f32x2 %0, %1, %2, %3;" : "=l"(d) : "l"(a), "l"(b), "l"(c)); return d;
}
__device__ __forceinline__ u64 mul2(u64 a, u64 b) {
    u64 d; asm("mul.rn.f32x2 %0, %1, %2;" : "=l"(d) : "l"(a), "l"(b)); return d;
}
__device__ __forceinline__ u64 add2(u64 a, u64 b) {
    u64 d; asm("add.rn.f32x2 %0, %1, %2;" : "=l"(d) : "l"(a), "l"(b)); return d;
}
__device__ __forceinline__ u64 neg2(u64 v) { return v ^ 0x8000000080000000ULL; }
__device__ __forceinline__ u64 sub2(u64 a, u64 b) { return add2(a, neg2(b)); }

// ---- scalar complex helpers (matrix construction only) ----
__device__ __forceinline__ float2 cmul(float2 a, float2 b) {
    return make_float2(fmaf(a.x, b.x, -a.y * b.y), fmaf(a.x, b.y, a.y * b.x));
}
__device__ __forceinline__ float2 cadd(float2 a, float2 b) { return make_float2(a.x + b.x, a.y + b.y); }
__device__ __forceinline__ float2 csub(float2 a, float2 b) { return make_float2(a.x - b.x, a.y - b.y); }
__device__ __forceinline__ float2 cscale(float s, float2 a) { return make_float2(s * a.x, s * a.y); }

// ---- GF(2)-linear address machinery ----
// smem swizzle: physc(j) = j ^ s(j>>5), s(a) = (a&15)|((a&8)<<1). LINEAR over GF(2):
// physc(u ^ v) == physc(u) ^ physc(v). So every access = base(t) ^ constexpr-offset(r).
__host__ __device__ constexpr int physc(int j) {
    int a = j >> 5;
    return j ^ ((a & 15) | ((a & 8) << 1));
}
__host__ __device__ constexpr int par10(int v) {
    v ^= v >> 8; v ^= v >> 4; v ^= v >> 2; v ^= v >> 1; return v & 1;
}
// CNOT-ring inverse permutation (linear; masks validated by measurement path)
__host__ __device__ constexpr int pinv10(int x) {
    int r = 0;
    for (int k = 0; k < 10; ++k) {
        int m = (k == 9) ? 0x1FF : (0x3FF & ~((1 << k) - 1));
        r |= par10(x & m) << k;
    }
    return r;
}
// scatter address: st'[j]=st[p(j)] scattered as sv[physc(pinv(x))] = amp_x. Linear.
__host__ __device__ constexpr int scatAddr(int x) { return physc(pinv10(x)); }

// real RY on register bit g: 8 disjoint pairs, 8 packed ops/pair
#define APPLY_RY(COptr, g) do {                                             \
    const ulonglong2 q_ = *(COptr);                                         \
    const u64 c_ = q_.x, s_ = q_.y, ns_ = neg2(s_);                         \
    const int bm_ = 1 << (g), lo_ = bm_ - 1;                                \
    _Pragma("unroll") for (int p_ = 0; p_ < 8; ++p_) {                      \
        const int i0_ = ((p_ & ~lo_) << 1) | (p_ & lo_);                    \
        const int i1_ = i0_ | bm_;                                          \
        u64 b0r = fma2(c_, re[i0_], mul2(ns_, re[i1_]));                    \
        u64 b0i = fma2(c_, im[i0_], mul2(ns_, im[i1_]));                    \
        u64 b1r = fma2(c_, re[i1_], mul2(s_,  re[i0_]));                    \
        u64 b1i = fma2(c_, im[i1_], mul2(s_,  im[i0_]));                    \
        re[i0_] = b0r; im[i0_] = b0i; re[i1_] = b1r; im[i1_] = b1i;         \
    }                                                                       \
} while (0)

// ---- diagonal event: gray-code running products, conj handled via tables ----
#define DIAG_APPLY_X(g_) do {                                               \
    u64 ar_ = fma2(re[g_], xr_, mul2(im[g_], nxi_));                        \
    u64 ai_ = fma2(re[g_], xi_, mul2(im[g_], xr_));                         \
    re[g_] = ar_; im[g_] = ai_; } while (0)

#define DIAG_APPLY_Y(g_) do {                                               \
    u64 ar_ = fma2(re[g_], yr_, mul2(im[g_], nyi_));                        \
    u64 ai_ = fma2(re[g_], yi_, mul2(im[g_], yr_));                         \
    re[g_] = ar_; im[g_] = ai_; } while (0)

#define DIAG_UPD_X(F_) do {                                                 \
    u64 nr_ = fma2(xr_, (F_).x, mul2(nxi_, (F_).y));                        \
    u64 ni_ = fma2(xr_, (F_).y, mul2(xi_,  (F_).x));                        \
    xr_ = nr_; xi_ = ni_; nxi_ = neg2(ni_); } while (0)

#define DIAG_UPD_Y(F_) do {                                                 \
    u64 nr_ = fma2(yr_, (F_).x, mul2(nyi_, (F_).y));                        \
    u64 ni_ = fma2(yr_, (F_).y, mul2(yi_,  (F_).x));                        \
    yr_ = nr_; yi_ = ni_; nyi_ = neg2(ni_); } while (0)

// gray walk over 3 bits: 0,1,3,2,6,7,5,4. CLR transitions use conj table (FBc).
#define APPLY_DIAG(FB, FBc, TW0, RW0) do {                                  \
    u64 xr_ = pk2(1.0f, 1.0f), xi_ = 0ULL, nxi_ = neg2(0ULL);               \
    _Pragma("unroll") for (int k_ = 0; k_ < 6; ++k_) {                      \
        const ulonglong2 f_ = (FB)[(TW0) - k_];                             \
        u64 nr_ = fma2(xr_, f_.x, mul2(nxi_, f_.y));                        \
        u64 ni_ = fma2(xr_, f_.y, mul2(xi_,  f_.x));                        \
        if ((t >> k_) & 1) { xr_ = nr_; xi_ = ni_; nxi_ = neg2(ni_); }      \
    }                                                                       \
    const ulonglong2 F0_ = (FB)[(RW0)];                                     \
    const ulonglong2 F1_ = (FB)[(RW0) - 1];                                 \
    const ulonglong2 F2_ = (FB)[(RW0) - 2];                                 \
    const ulonglong2 F3_ = (FB)[(RW0) - 3];                                 \
    const ulonglong2 G0_ = (FBc)[(RW0)];                                    \
    const ulonglong2 G1_ = (FBc)[(RW0) - 1];                                \
    u64 yr_ = fma2(xr_, F3_.x, mul2(nxi_, F3_.y));                          \
    u64 yi_ = fma2(xr_, F3_.y, mul2(xi_,  F3_.x));                          \
    u64 nyi_ = neg2(yi_);                                                   \
    DIAG_APPLY_X(0);                  DIAG_APPLY_Y(8);                      \
    DIAG_UPD_X(F0_); DIAG_APPLY_X(1); DIAG_UPD_Y(F0_); DIAG_APPLY_Y(9);     \
    DIAG_UPD_X(F1_); DIAG_APPLY_X(3); DIAG_UPD_Y(F1_); DIAG_APPLY_Y(11);    \
    DIAG_UPD_X(G0_); DIAG_APPLY_X(2); DIAG_UPD_Y(G0_); DIAG_APPLY_Y(10);    \
    DIAG_UPD_X(F2_); DIAG_APPLY_X(6); DIAG_UPD_Y(F2_); DIAG_APPLY_Y(14);    \
    DIAG_UPD_X(F0_); DIAG_APPLY_X(7); DIAG_UPD_Y(F0_); DIAG_APPLY_Y(15);    \
    DIAG_UPD_X(G1_); DIAG_APPLY_X(5); DIAG_UPD_Y(G1_); DIAG_APPLY_Y(13);    \
    DIAG_UPD_X(G0_); DIAG_APPLY_X(4); DIAG_UPD_Y(G0_); DIAG_APPLY_Y(12);    \
} while (0)

__global__ __launch_bounds__(NT, 9)
void quantum_layer_kernel(const float* __restrict__ x,
                          const float* __restrict__ weight,
                          float* __restrict__ out)
{
    __shared__ ulonglong2 sv[DIM];            // 16 KB: (re_pk2, im_pk2)
    __shared__ ulonglong2 ry[NLAYERS][NQ];    // (c, s) RY(delta) coeffs, packed
    __shared__ ulonglong2 Fe[NLAYERS][NQ];    // e^{i*eps_w}  (cos, sin)
    __shared__ ulonglong2 FeC[NLAYERS][NQ];   // conj
    __shared__ ulonglong2 Fg[NLAYERS][NQ];    // e^{i*gamma_w}
    __shared__ ulonglong2 FgC[NLAYERS][NQ];   // conj
    __shared__ u64 wred[2][NQ];               // cross-warp measurement reduce

    const int t  = threadIdx.x;               // 0..63
    const int b0 = blockIdx.x * 2, b1 = b0 + 1;

    // ---- per-wire ZYZ: M = RZ(gamma)*RY(delta)*RZ(eps) (scalar prefactors are
    // global phases, dropped). c=|m00|, s=|m10|, gamma=av-au, eps=-av-au.
    if (t < NQ) {
        const int w = t;
        float ang[2];
        ang[0] = tanhf(x[b0 * NQ + w]) * PI_F;
        ang[1] = tanhf(x[b1 * NQ + w]) * PI_F;
        for (int l = 0; l < NLAYERS; ++l) {
            float th1 = weight[(l * NQ + w) * 3 + 0];
            float th2 = weight[(l * NQ + w) * 3 + 1];
            float th3 = weight[(l * NQ + w) * 3 + 2];
            float cc[2], ss[2], ger[2], gei[2], eer[2], eei[2];
            #pragma unroll
            for (int bb = 0; bb < 2; ++bb) {
                float s0, c0, s1, c1, s2, c2, s3, c3;
                __sincosf(0.5f * ang[bb], &s0, &c0);
                __sincosf(0.5f * th1, &s1, &c1);
                __sincosf(0.5f * th2, &s2, &c2);
                __sincosf(0.5f * th3, &s3, &c3);
                float2 d1m = make_float2(c1, -s1), d1p = make_float2(c1, s1);
                float2 d3m = make_float2(c3, -s3), d3p = make_float2(c3, s3);
                // u = m00, v = m10 of the fused SU(2) matrix
                float2 u = cmul(d3m, csub(cscale(c2 * c0, d1m), cscale(s2 * s0, d1p)));
                float2 v = cmul(d3p, cadd(cscale(s2 * c0, d1m), cscale(c2 * s0, d1p)));
                cc[bb] = sqrtf(fmaf(u.x, u.x, u.y * u.y));
                ss[bb] = sqrtf(fmaf(v.x, v.x, v.y * v.y));
                float au = atan2f(u.y, u.x);
                float av = atan2f(v.y, v.x);
                float sg, cg, se, ce;
                __sincosf(av - au, &sg, &cg);    // e^{i*gamma}
                __sincosf(-av - au, &se, &ce);   // e^{i*eps}
                ger[bb] = cg; gei[bb] = sg; eer[bb] = ce; eei[bb] = se;
            }
            ry[l][w]  = make_ulonglong2(pk2(cc[0], cc[1]), pk2(ss[0], ss[1]));
            u64 gr = pk2(ger[0], ger[1]), gi = pk2(gei[0], gei[1]);
            u64 er = pk2(eer[0], eer[1]), ei = pk2(eei[0], eei[1]);
            Fg[l][w]  = make_ulonglong2(gr, gi);
            FgC[l][w] = make_ulonglong2(gr, neg2(gi));
            Fe[l][w]  = make_ulonglong2(er, ei);
            FeC[l][w] = make_ulonglong2(er, neg2(ei));
        }
    }
    __syncthreads();

    // ---- linear address bases (one-time per thread); offsets are constexpr
    const int tbhi = (t >> 4) << 8, tblo = t & 15;
    const int baseA = physc(t << 4);        // A: addr = baseA ^ r           (physc(r)=r, r<16)
    const int baseB = physc(tbhi | tblo);   // B: addr = baseB ^ physc(r<<4)
    const int baseC = physc(t);             // C: addr = baseC ^ physc(r<<6)
    const int baseS = scatAddr(t);          // scatter: addr = baseS ^ scatAddr(r<<6)

    // ---- state: 16 amps/thread, three arrangements per layer:
    //  A: j = (t<<4)|r                 r bits 0..3 = wires 9..6; t bits 0..5 = wires 5..0
    //  B: j = tbhi|(r<<4)|tblo         r bits 0..3 = wires 5..2
    //  C: j = (r<<6)|t                 r bits 0..3 = wires 3..0; t bits 0..5 = wires 9..4
    u64 re[16], im[16];

    #pragma unroll 1
    for (int l = 0; l < NLAYERS; ++l) {
        // ===== arrangement A: D_eps(l) (l>=1; eps_0 is a global phase), RY wires 9..6
        if (l == 0) {
            // |0..0>: pure-RY column-0 products on thread 0 (real)
            #pragma unroll
            for (int i = 0; i < 16; ++i) { re[i] = 0ULL; im[i] = 0ULL; }
            if (t == 0) {
                #pragma unroll
                for (int r = 0; r < 16; ++r) {
                    u64 v = pk2(1.0f, 1.0f);
                    #pragma unroll
                    for (int g = 0; g < 4; ++g) {
                        const ulonglong2 q = ry[0][9 - g];
                        v = mul2(v, ((r >> g) & 1) ? q.y : q.x);
                    }
                    re[r] = v;
                }
            }
        } else {
            #pragma unroll
            for (int r = 0; r < 16; ++r) {
                ulonglong2 v = sv[baseA ^ r];
                re[r] = v.x; im[r] = v.y;
            }
            APPLY_DIAG(&Fe[l][0], &FeC[l][0], 5, 9);   // eps: t->wires 5..0, r->wires 9..6
            APPLY_RY(&ry[l][9], 0);
            APPLY_RY(&ry[l][8], 1);
            APPLY_RY(&ry[l][7], 2);
            APPLY_RY(&ry[l][6], 3);
        }
        #pragma unroll
        for (int r = 0; r < 16; ++r)
            sv[baseA ^ r] = make_ulonglong2(re[r], im[r]);
        __syncthreads();

        // ===== arrangement B: RY wires 5..2
        #pragma unroll
        for (int r = 0; r < 16; ++r) {
            ulonglong2 v = sv[baseB ^ physc(r << 4)];
            re[r] = v.x; im[r] = v.y;
        }
        APPLY_RY(&ry[l][5], 0);
        APPLY_RY(&ry[l][4], 1);
        APPLY_RY(&ry[l][3], 2);
        APPLY_RY(&ry[l][2], 3);
        #pragma unroll
        for (int r = 0; r < 16; ++r)
            sv[baseB ^ physc(r << 4)] = make_ulonglong2(re[r], im[r]);
        __syncthreads();

        // ===== arrangement C: RY wires 1,0; D_gamma(l) (l<=2; gamma_3 invisible in |.|^2)
        #pragma unroll
        for (int r = 0; r < 16; ++r) {
            ulonglong2 v = sv[baseC ^ physc(r << 6)];
            re[r] = v.x; im[r] = v.y;
        }
        APPLY_RY(&ry[l][1], 2);
        APPLY_RY(&ry[l][0], 3);
        if (l < NLAYERS - 1) {
            APPLY_DIAG(&Fg[l][0], &FgC[l][0], 9, 3);   // gamma: t->wires 9..4, r->wires 3..0
            __syncthreads();                   // all C loads done before permuted scatter
            #pragma unroll
            for (int r = 0; r < 16; ++r)
                sv[baseS ^ scatAddr(r << 6)] = make_ulonglong2(re[r], im[r]);
            __syncthreads();
        }
    }

    // ---- measurement in arrangement C: amp x = (r<<6)|t.
    // Final CNOT ring folded into signs: sign_w(x) = parity(x & mask_{9-w}),
    // mask_k = bits k..9 (k<=8), mask_9 = 0x1FF.
    #pragma unroll
    for (int i = 0; i < 16; ++i)
        re[i] = fma2(re[i], re[i], mul2(im[i], im[i]));   // packed |amp|^2

    // r-parity partial sums: only mr in {15,14,12,7} occur.
    u64 S[8], A[8];
    #pragma unroll
    for (int i = 0; i < 8; ++i) { S[i] = add2(re[i], re[i + 8]); A[i] = sub2(re[i], re[i + 8]); }
    u64 S2[4], B4[4];
    #pragma unroll
    for (int i = 0; i < 4; ++i) { S2[i] = sub2(S[i], S[i + 4]); B4[i] = sub2(A[i], A[i + 4]); }
    u64 S21_0 = sub2(S2[0], S2[2]), S21_1 = sub2(S2[1], S2[3]);
    u64 C2_0 = sub2(B4[0], B4[2]), C2_1 = sub2(B4[1], B4[3]);
    u64 P7  = sub2(S21_0, S21_1);                   // parity(r & 0b0111), summed over bit3
    u64 P15 = sub2(C2_0, C2_1);                     // parity(r & 0b1111)
    u64 P14 = add2(C2_0, C2_1);                     // parity(r & 0b1110)
    u64 P12 = add2(add2(B4[0], B4[1]), add2(B4[2], B4[3]));   // parity(r & 0b1100)

    const int warp = t >> 5;
    const unsigned fullmask = 0xffffffffu;
    #pragma unroll
    for (int w = 0; w < NQ; ++w) {
        const int k = 9 - w;
        const unsigned mask = (k == 9) ? 0x1FFu : (0x3FFu & ~((1u << k) - 1u));
        const unsigned mr = (mask >> 6) & 15u, mt = mask & 63u;
        u64 acc = (mr == 15u) ? P15 : (mr == 14u) ? P14 : (mr == 12u) ? P12 : P7;
        if (__popc((unsigned)t & mt) & 1) acc = neg2(acc);
        #pragma unroll
        for (int off = 16; off; off >>= 1) {
            u64 o = __shfl_xor_sync(fullmask, acc, off);
            acc = add2(acc, o);
        }
        if ((t & 31) == 0) wred[warp][w] = acc;
    }
    __syncthreads();
    if (t < NQ) {
        u64 s = add2(wred[0][t], wred[1][t]);
        float ra, rb; upk2(s, ra, rb);
        out[b0 * NQ + t] = ra;
        out[b1 * NQ + t] = rb;
    }
}

extern "C" void kernel_launch(void* const* d_in, const int* in_sizes, int n_in,
                              void* d_out, int out_size) {
    const float* x      = (const float*)d_in[0];   // (16384, 10) float32
    const float* weight = (const float*)d_in[1];   // (4, 10, 3)  float32
    float* out          = (float*)d_out;           // (16384, 10) float32
    const int batch  = in_sizes[0] / NQ;
    const int blocks = batch / 2;                  // 2 batch elems per block
    quantum_layer_kernel<<<blocks, NT>>>(x, weight, out);
}

// round 15
// speedup vs baseline: 1.0498x; 1.0498x over previous
#include <cuda_runtime.h>

#define NQ       10
#define DIM      1024
#define NLAYERS  4
#define NT       64           // 2 warps/block; EACH WARP owns one full state (1 batch elem)
#define PI_F     3.14159265358979323846f

typedef unsigned long long u64;

// ---- packed f32x2 helpers: ONE amp per u64 (re in lo, im in hi) ----
__device__ __forceinline__ u64 pk2(float lo, float hi) {
    u64 r; asm("mov.b64 %0, {%1, %2};" : "=l"(r) : "f"(lo), "f"(hi)); return r;
}
__device__ __forceinline__ void upk2(u64 v, float& lo, float& hi) {
    asm("mov.b64 {%0, %1}, %2;" : "=f"(lo), "=f"(hi) : "l"(v));
}
__device__ __forceinline__ u64 fma2(u64 a, u64 b, u64 c) {
    u64 d; asm("fma.rn.f32x2 %0, %1, %2, %3;" : "=l"(d) : "l"(a), "l"(b), "l"(c)); return d;
}
__device__ __forceinline__ u64 mul2(u64 a, u64 b) {
    u64 d; asm("mul.rn.f32x2 %0, %1, %2;" : "=l"(d) : "l"(a), "l"(b)); return d;
}
__device__ __forceinline__ u64 neg2(u64 v) { return v ^ 0x8000000080000000ULL; }
__device__ __forceinline__ u64 swapu(u64 v) {
    float lo, hi; upk2(v, lo, hi); return pk2(hi, lo);
}

// ---- scalar complex helpers (coefficient construction only) ----
__device__ __forceinline__ float2 cmul(float2 a, float2 b) {
    return make_float2(fmaf(a.x, b.x, -a.y * b.y), fmaf(a.x, b.y, a.y * b.x));
}
__device__ __forceinline__ float2 cadd(float2 a, float2 b) { return make_float2(a.x + b.x, a.y + b.y); }
__device__ __forceinline__ float2 csub(float2 a, float2 b) { return make_float2(a.x - b.x, a.y - b.y); }
__device__ __forceinline__ float2 cscale(float s, float2 a) { return make_float2(s * a.x, s * a.y); }

// ---- GF(2)-linear address machinery (pinv masks validated since R9/R13) ----
__host__ __device__ constexpr int phys32(int j) { return j ^ (j >> 5); }
__host__ __device__ constexpr int par10(int v) {
    v ^= v >> 8; v ^= v >> 4; v ^= v >> 2; v ^= v >> 1; return v & 1;
}
__host__ __device__ constexpr int pinv10(int x) {
    int r = 0;
    for (int k = 0; k < 10; ++k) {
        int m = (k == 9) ? 0x1FF : (0x3FF & ~((1 << k) - 1));
        r |= par10(x & m) << k;
    }
    return r;
}
__host__ __device__ constexpr int scOff(int r) { return phys32(pinv10(r << 5)); }
__host__ __device__ constexpr int offB(int r) { return (r << 5) | r; }   // phys32(r<<5)

// ---- real RY on register bit g over 32 amps: 16 disjoint pairs, 4 ops/pair ----
#define APPLY_RY5(Q_, g) do {                                               \
    const ulonglong2 q_ = (Q_);                                             \
    const u64 c_ = q_.x, s_ = q_.y, ns_ = neg2(s_);                         \
    const int bm_ = 1 << (g), lo_ = bm_ - 1;                                \
    _Pragma("unroll") for (int p_ = 0; p_ < 16; ++p_) {                     \
        const int i0_ = ((p_ & ~lo_) << 1) | (p_ & lo_);                    \
        const int i1_ = i0_ | bm_;                                          \
        u64 n0_ = fma2(c_, v[i0_], mul2(ns_, v[i1_]));                      \
        u64 n1_ = fma2(c_, v[i1_], mul2(s_,  v[i0_]));                      \
        v[i0_] = n0_; v[i1_] = n1_;                                         \
    }                                                                       \
} while (0)

// ---- diagonal machinery on (re,im)-packed amps ----
// Chain state: Rr = (zr,zr) dup, Rn = (-zi,zi) anti-dup.
// Factor tables per wire: [0]=FX=(fr,fr), [1]=FYn=(-fi,fi), [2]=FYp=(fi,-fi).
// forward z*=f:  Rr' = Rn*FYp + Rr*FX ; Rn' = Rr*FYn + Rn*FX   (4 ops, no LOP)
// conj    z*=f*: Rr' = Rn*FYn + Rr*FX ; Rn' = Rr*FYp + Rn*FX
#define DFWD(Rr, Rn, W_) do {                                               \
    u64 fx_ = FB_[(W_)][0], fyn_ = FB_[(W_)][1], fyp_ = FB_[(W_)][2];       \
    u64 nr_ = fma2(Rn, fyp_, mul2(Rr, fx_));                                \
    u64 nn_ = fma2(Rr, fyn_, mul2(Rn, fx_));                                \
    Rr = nr_; Rn = nn_; } while (0)
#define DCNJ(Rr, Rn, W_) do {                                               \
    u64 fx_ = FB_[(W_)][0], fyn_ = FB_[(W_)][1], fyp_ = FB_[(W_)][2];       \
    u64 nr_ = fma2(Rn, fyn_, mul2(Rr, fx_));                                \
    u64 nn_ = fma2(Rr, fyp_, mul2(Rn, fx_));                                \
    Rr = nr_; Rn = nn_; } while (0)
// amp *= z : v' = Rr*v + Rn*swap(v)
#define APZ(i_, Rr, Rn) do {                                                \
    u64 w_ = swapu(v[i_]);                                                  \
    v[i_] = fma2(Rr, v[i_], mul2(Rn, w_)); } while (0)
#define APS4(n_) do { APZ((n_), Xr_, Xn_); APZ((n_) + 8, Yr_, Yn_);         \
    APZ((n_) + 16, Zr_, Zn_); APZ((n_) + 24, Wr_, Wn_); } while (0)
#define UPD4F(W_) do { DFWD(Xr_,Xn_,W_); DFWD(Yr_,Yn_,W_);                  \
    DFWD(Zr_,Zn_,W_); DFWD(Wr_,Wn_,W_); } while (0)
#define UPD4C(W_) do { DCNJ(Xr_,Xn_,W_); DCNJ(Yr_,Yn_,W_);                  \
    DCNJ(Zr_,Zn_,W_); DCNJ(Wr_,Wn_,W_); } while (0)

// full-state diagonal: lane bit k -> wire TW0-k; reg bit b -> wire RW0-b.
// 4 sub-chains (X, X*F3, X*F4, X*F3*F4) walk the 3-bit gray 0,1,3,2,6,7,5,4.
#define APPLY_DIAG5(FBP, TW0, RW0) do {                                     \
    const u64 (*FB_)[3] = (FBP);                                            \
    u64 Xr_ = pk2(1.0f, 1.0f), Xn_ = 0ULL;                                  \
    _Pragma("unroll") for (int k_ = 0; k_ < 5; ++k_) {                      \
        u64 fx_ = FB_[(TW0) - k_][0], fyn_ = FB_[(TW0) - k_][1],            \
            fyp_ = FB_[(TW0) - k_][2];                                      \
        u64 nr_ = fma2(Xn_, fyp_, mul2(Xr_, fx_));                          \
        u64 nn_ = fma2(Xr_, fyn_, mul2(Xn_, fx_));                          \
        if ((lane >> k_) & 1) { Xr_ = nr_; Xn_ = nn_; }                     \
    }                                                                       \
    u64 Yr_ = Xr_, Yn_ = Xn_; DFWD(Yr_, Yn_, (RW0) - 3);                    \
    u64 Zr_ = Xr_, Zn_ = Xn_; DFWD(Zr_, Zn_, (RW0) - 4);                    \
    u64 Wr_ = Yr_, Wn_ = Yn_; DFWD(Wr_, Wn_, (RW0) - 4);                    \
    APS4(0);                                                                \
    UPD4F((RW0));     APS4(1);                                              \
    UPD4F((RW0) - 1); APS4(3);                                              \
    UPD4C((RW0));     APS4(2);                                              \
    UPD4F((RW0) - 2); APS4(6);                                              \
    UPD4F((RW0));     APS4(7);                                              \
    UPD4C((RW0) - 1); APS4(5);                                              \
    UPD4C((RW0));     APS4(4);                                              \
} while (0)

__global__ __launch_bounds__(NT, 8)
void quantum_layer_kernel(const float* __restrict__ x,
                          const float* __restrict__ weight,
                          float* __restrict__ out)
{
    __shared__ u64 sv[2][DIM];                 // 16 KB: per-warp statevector, 8B/amp
    __shared__ ulonglong2 RY[2][NLAYERS][NQ];  // (c dup, s dup)
    __shared__ u64 FE[2][NLAYERS][NQ][3];      // eps factors: FX, FYn, FYp
    __shared__ u64 FG[2][NLAYERS][NQ][3];      // gamma factors

    const int tid  = threadIdx.x;
    const int wp   = tid >> 5;
    const int lane = tid & 31;
    const int b    = blockIdx.x * 2 + wp;      // this warp's batch element
    u64* __restrict__ svw = sv[wp];

    // ---- per-wire ZYZ coefficients (single batch; lanes 0..9) ----
    if (lane < NQ) {
        const int w = lane;
        float ang = tanhf(x[b * NQ + w]) * PI_F;
        for (int l = 0; l < NLAYERS; ++l) {
            float th1 = weight[(l * NQ + w) * 3 + 0];
            float th2 = weight[(l * NQ + w) * 3 + 1];
            float th3 = weight[(l * NQ + w) * 3 + 2];
            float s0, c0, s1, c1, s2, c2, s3, c3;
            __sincosf(0.5f * ang, &s0, &c0);
            __sincosf(0.5f * th1, &s1, &c1);
            __sincosf(0.5f * th2, &s2, &c2);
            __sincosf(0.5f * th3, &s3, &c3);
            float2 d1m = make_float2(c1, -s1), d1p = make_float2(c1, s1);
            float2 d3m = make_float2(c3, -s3), d3p = make_float2(c3, s3);
            // u = m00, v = m10 of the fused SU(2) matrix
            float2 u = cmul(d3m, csub(cscale(c2 * c0, d1m), cscale(s2 * s0, d1p)));
            float2 vv = cmul(d3p, cadd(cscale(s2 * c0, d1m), cscale(c2 * s0, d1p)));
            float c = sqrtf(fmaf(u.x, u.x, u.y * u.y));
            float s = sqrtf(fmaf(vv.x, vv.x, vv.y * vv.y));
            float au = atan2f(u.y, u.x);
            float av = atan2f(vv.y, vv.x);
            float sg, cg, se, ce;
            __sincosf(av - au, &sg, &cg);    // e^{i*gamma}
            __sincosf(-av - au, &se, &ce);   // e^{i*eps}
            RY[wp][l][w] = make_ulonglong2(pk2(c, c), pk2(s, s));
            FE[wp][l][w][0] = pk2(ce, ce);
            FE[wp][l][w][1] = pk2(-se, se);
            FE[wp][l][w][2] = pk2(se, -se);
            FG[wp][l][w][0] = pk2(cg, cg);
            FG[wp][l][w][1] = pk2(-sg, sg);
            FG[wp][l][w][2] = pk2(sg, -sg);
        }
    }
    __syncwarp();

    // ---- state: 32 amps/thread, TWO arrangements per layer:
    //  A: j = (lane<<5)|r   reg bit b -> wire 9-b (wires 9..5); lane bit k -> wire 4-k
    //  B: j = (r<<5)|lane   reg bit b -> wire 4-b (wires 4..0); lane bit k -> wire 9-k
    u64 v[32];

    const int baseA = (lane << 5) | lane;          // phys32(lane<<5)
    const int baseB = lane;                        // phys32(lane)
    const int baseS = phys32(pinv10(lane));        // scatter lane base

    #pragma unroll 1
    for (int l = 0; l < NLAYERS; ++l) {
        if (l == 0) {
            // |0..0>: after A-gates only amps j<32 nonzero; in B arrangement
            // that is exactly v[0] = prod over lane bits (set ? s : c), wire 9-b.
            #pragma unroll
            for (int i = 0; i < 32; ++i) v[i] = 0ULL;
            float f = 1.0f;
            #pragma unroll
            for (int bb = 0; bb < 5; ++bb) {
                ulonglong2 q = RY[wp][0][9 - bb];
                float cv, d0, sve, d1;
                upk2(q.x, cv, d0); upk2(q.y, sve, d1);
                f *= ((lane >> bb) & 1) ? sve : cv;
            }
            v[0] = pk2(f, 0.0f);
        } else {
            // ===== arrangement A: eps diag, then RY wires 9..5
            #pragma unroll
            for (int r = 0; r < 32; ++r) v[r] = svw[baseA ^ r];
            APPLY_DIAG5(FE[wp][l], 4, 9);
            APPLY_RY5(RY[wp][l][9], 0);
            APPLY_RY5(RY[wp][l][8], 1);
            APPLY_RY5(RY[wp][l][7], 2);
            APPLY_RY5(RY[wp][l][6], 3);
            APPLY_RY5(RY[wp][l][5], 4);
            #pragma unroll
            for (int r = 0; r < 32; ++r) svw[baseA ^ r] = v[r];
            __syncwarp();
            // ===== load arrangement B
            #pragma unroll
            for (int r = 0; r < 32; ++r) v[r] = svw[offB(r) ^ baseB];
            __syncwarp();   // all B loads done before any scatter overwrite
        }
        // ===== arrangement B: RY wires 4..0
        APPLY_RY5(RY[wp][l][4], 0);
        APPLY_RY5(RY[wp][l][3], 1);
        APPLY_RY5(RY[wp][l][2], 2);
        APPLY_RY5(RY[wp][l][1], 3);
        APPLY_RY5(RY[wp][l][0], 4);
        if (l < NLAYERS - 1) {
            APPLY_DIAG5(FG[wp][l], 9, 4);          // gamma before CNOT ring
            #pragma unroll
            for (int r = 0; r < 32; ++r) svw[baseS ^ scOff(r)] = v[r];
            __syncwarp();
        }
    }

    // ---- measurement in arrangement B: amp x = (r<<5)|lane.
    // Final CNOT ring folded into signs: sign_w(x) = parity(x & mask_{9-w}),
    // mask_k = bits k..9 (k<=8), mask_9 = 0x1FF.
    float pp[32];
    #pragma unroll
    for (int r = 0; r < 32; ++r) {
        float a, bb; upk2(mul2(v[r], v[r]), a, bb);
        pp[r] = a + bb;
    }
    // reg-part parity partial sums over reg bits (j bits 5..9):
    // needed masks mr in {31,30,28,24,15}.
    float e[16], o[16];
    #pragma unroll
    for (int i = 0; i < 16; ++i) { e[i] = pp[2*i] - pp[2*i+1]; o[i] = pp[2*i] + pp[2*i+1]; }
    float f1[8], g1[8], h[8];
    #pragma unroll
    for (int i = 0; i < 8; ++i) { f1[i] = e[2*i] - e[2*i+1]; g1[i] = o[2*i] - o[2*i+1];
                                  h[i]  = o[2*i] + o[2*i+1]; }
    float f2[4], g2[4], k2[4], m2[4];
    #pragma unroll
    for (int i = 0; i < 4; ++i) { f2[i] = f1[2*i] - f1[2*i+1]; g2[i] = g1[2*i] - g1[2*i+1];
                                  k2[i] = h[2*i]  - h[2*i+1];  m2[i] = h[2*i]  + h[2*i+1]; }
    float f3a = f2[0] - f2[1], f3b = f2[2] - f2[3];
    float g3a = g2[0] - g2[1], g3b = g2[2] - g2[3];
    float k3a = k2[0] - k2[1], k3b = k2[2] - k2[3];
    float m3a = m2[0] - m2[1], m3b = m2[2] - m2[3];
    const float P31 = f3a - f3b;   // reg bits 0..4 signed
    const float P15 = f3a + f3b;   // reg bits 0..3
    const float P30 = g3a - g3b;   // reg bits 1..4
    const float P28 = k3a - k3b;   // reg bits 2..4
    const float P24 = m3a - m3b;   // reg bits 3..4

    const unsigned fullmask = 0xffffffffu;
    #pragma unroll
    for (int k = 0; k < NQ; ++k) {
        float acc = (k <= 5) ? P31 : (k == 6) ? P30 : (k == 7) ? P28
                  : (k == 8) ? P24 : P15;
        const unsigned mt = (k == 0 || k == 9) ? 31u : (k == 1) ? 30u
                          : (k == 2) ? 28u : (k == 3) ? 24u : (k == 4) ? 16u : 0u;
        if (mt && (__popc((unsigned)lane & mt) & 1)) acc = -acc;
        #pragma unroll
        for (int off = 16; off; off >>= 1)
            acc += __shfl_xor_sync(fullmask, acc, off);
        if (lane == 0) out[b * NQ + (9 - k)] = acc;
    }
}

extern "C" void kernel_launch(void* const* d_in, const int* in_sizes, int n_in,
                              void* d_out, int out_size) {
    const float* x      = (const float*)d_in[0];   // (16384, 10) float32
    const float* weight = (const float*)d_in[1];   // (4, 10, 3)  float32
    float* out          = (float*)d_out;           // (16384, 10) float32
    const int batch  = in_sizes[0] / NQ;
    const int blocks = batch / 2;                  // 2 batch elems per block (1/warp)
    quantum_layer_kernel<<<blocks, NT>>>(x, weight, out);
}

// round 17
// speedup vs baseline: 1.0600x; 1.0097x over previous
#include <cuda_runtime.h>

#define NQ       10
#define DIM      1024
#define NLAYERS  4
#define NT       64           // 2 warps/block; EACH WARP owns one full state (1 batch elem)
#define PI_F     3.14159265358979323846f

typedef unsigned long long u64;

// ---- packed f32x2 helpers: ONE amp per u64 (re in lo, im in hi) ----
__device__ __forceinline__ u64 pk2(float lo, float hi) {
    u64 r; asm("mov.b64 %0, {%1, %2};" : "=l"(r) : "f"(lo), "f"(hi)); return r;
}
__device__ __forceinline__ void upk2(u64 v, float& lo, float& hi) {
    asm("mov.b64 {%0, %1}, %2;" : "=f"(lo), "=f"(hi) : "l"(v));
}
__device__ __forceinline__ u64 fma2(u64 a, u64 b, u64 c) {
    u64 d; asm("fma.rn.f32x2 %0, %1, %2, %3;" : "=l"(d) : "l"(a), "l"(b), "l"(c)); return d;
}
__device__ __forceinline__ u64 mul2(u64 a, u64 b) {
    u64 d; asm("mul.rn.f32x2 %0, %1, %2;" : "=l"(d) : "l"(a), "l"(b)); return d;
}
__device__ __forceinline__ u64 neg2(u64 v) { return v ^ 0x8000000080000000ULL; }
__device__ __forceinline__ u64 swapu(u64 v) {
    float lo, hi; upk2(v, lo, hi); return pk2(hi, lo);
}

// ---- scalar complex helpers (coefficient construction only) ----
__device__ __forceinline__ float2 cmul(float2 a, float2 b) {
    return make_float2(fmaf(a.x, b.x, -a.y * b.y), fmaf(a.x, b.y, a.y * b.x));
}
__device__ __forceinline__ float2 cadd(float2 a, float2 b) { return make_float2(a.x + b.x, a.y + b.y); }
__device__ __forceinline__ float2 csub(float2 a, float2 b) { return make_float2(a.x - b.x, a.y - b.y); }
__device__ __forceinline__ float2 cscale(float s, float2 a) { return make_float2(s * a.x, s * a.y); }

// ---- GF(2)-linear address machinery (pinv masks validated since R9/R13/R15) ----
__host__ __device__ constexpr int phys32(int j) { return j ^ (j >> 5); }
__host__ __device__ constexpr int par10(int v) {
    v ^= v >> 8; v ^= v >> 4; v ^= v >> 2; v ^= v >> 1; return v & 1;
}
__host__ __device__ constexpr int pinv10(int x) {
    int r = 0;
    for (int k = 0; k < 10; ++k) {
        int m = (k == 9) ? 0x1FF : (0x3FF & ~((1 << k) - 1));
        r |= par10(x & m) << k;
    }
    return r;
}
__host__ __device__ constexpr int scOff(int r) { return phys32(pinv10(r << 5)); }
__host__ __device__ constexpr int offB(int r) { return (r << 5) | r; }   // phys32(r<<5)

// ---- real RY on register bit g over 32 amps: 16 disjoint pairs, 4 ops/pair ----
#define APPLY_RY5(Q_, g) do {                                               \
    const ulonglong2 q_ = (Q_);                                             \
    const u64 c_ = q_.x, s_ = q_.y, ns_ = neg2(s_);                         \
    const int bm_ = 1 << (g), lo_ = bm_ - 1;                                \
    _Pragma("unroll") for (int p_ = 0; p_ < 16; ++p_) {                     \
        const int i0_ = ((p_ & ~lo_) << 1) | (p_ & lo_);                    \
        const int i1_ = i0_ | bm_;                                          \
        u64 n0_ = fma2(c_, v[i0_], mul2(ns_, v[i1_]));                      \
        u64 n1_ = fma2(c_, v[i1_], mul2(s_,  v[i0_]));                      \
        v[i0_] = n0_; v[i1_] = n1_;                                         \
    }                                                                       \
} while (0)

// ---- diagonal machinery on (re,im)-packed amps ----
// Chain state: Rr = (zr,zr) dup, Rn = (-zi,zi) anti-dup.
// Factor tables per wire: [0]=FX=(fr,fr), [1]=FYn=(-fi,fi), [2]=FYp=(fi,-fi).
#define DFWD(Rr, Rn, W_) do {                                               \
    u64 fx_ = FB_[(W_)][0], fyn_ = FB_[(W_)][1], fyp_ = FB_[(W_)][2];       \
    u64 nr_ = fma2(Rn, fyp_, mul2(Rr, fx_));                                \
    u64 nn_ = fma2(Rr, fyn_, mul2(Rn, fx_));                                \
    Rr = nr_; Rn = nn_; } while (0)
#define DCNJ(Rr, Rn, W_) do {                                               \
    u64 fx_ = FB_[(W_)][0], fyn_ = FB_[(W_)][1], fyp_ = FB_[(W_)][2];       \
    u64 nr_ = fma2(Rn, fyn_, mul2(Rr, fx_));                                \
    u64 nn_ = fma2(Rr, fyp_, mul2(Rn, fx_));                                \
    Rr = nr_; Rn = nn_; } while (0)
// amp *= z : v' = Rr*v + Rn*swap(v)
#define APZ(i_, Rr, Rn) do {                                                \
    u64 w_ = swapu(v[i_]);                                                  \
    v[i_] = fma2(Rr, v[i_], mul2(Rn, w_)); } while (0)
#define APZ2_(g_)  do { APZ((g_), Xr_, Xn_); APZ((g_) + 16, Yr_, Yn_); } while (0)
#define UPD2F(W_)  do { DFWD(Xr_, Xn_, (W_)); DFWD(Yr_, Yn_, (W_)); } while (0)
#define UPD2C(W_)  do { DCNJ(Xr_, Xn_, (W_)); DCNJ(Yr_, Yn_, (W_)); } while (0)

// full-state diagonal: lane bit k -> wire TW0-k; reg bit b -> wire RW0-b.
// TWO sub-chains (X over reg bits 0..3 via 4-bit gray walk; Y = X * F[RW0-4]
// covering reg bit 4). Gray sequence 0,1,3,2,6,7,5,4,12,13,15,14,10,11,9,8.
#define APPLY_DIAG5(FBP, TW0, RW0) do {                                     \
    const u64 (*FB_)[3] = (FBP);                                            \
    u64 Xr_ = pk2(1.0f, 1.0f), Xn_ = 0ULL;                                  \
    _Pragma("unroll") for (int k_ = 0; k_ < 5; ++k_) {                      \
        u64 fx_ = FB_[(TW0) - k_][0], fyn_ = FB_[(TW0) - k_][1],            \
            fyp_ = FB_[(TW0) - k_][2];                                      \
        u64 nr_ = fma2(Xn_, fyp_, mul2(Xr_, fx_));                          \
        u64 nn_ = fma2(Xr_, fyn_, mul2(Xn_, fx_));                          \
        if ((lane >> k_) & 1) { Xr_ = nr_; Xn_ = nn_; }                     \
    }                                                                       \
    u64 Yr_ = Xr_, Yn_ = Xn_; DFWD(Yr_, Yn_, (RW0) - 4);                    \
    APZ2_(0);                                                               \
    UPD2F((RW0));     APZ2_(1);                                             \
    UPD2F((RW0) - 1); APZ2_(3);                                             \
    UPD2C((RW0));     APZ2_(2);                                             \
    UPD2F((RW0) - 2); APZ2_(6);                                             \
    UPD2F((RW0));     APZ2_(7);                                             \
    UPD2C((RW0) - 1); APZ2_(5);                                             \
    UPD2C((RW0));     APZ2_(4);                                             \
    UPD2F((RW0) - 3); APZ2_(12);                                            \
    UPD2F((RW0));     APZ2_(13);                                            \
    UPD2F((RW0) - 1); APZ2_(15);                                            \
    UPD2C((RW0));     APZ2_(14);                                            \
    UPD2C((RW0) - 2); APZ2_(10);                                            \
    UPD2F((RW0));     APZ2_(11);                                            \
    UPD2C((RW0) - 1); APZ2_(9);                                             \
    UPD2C((RW0));     APZ2_(8);                                             \
} while (0)

__global__ __launch_bounds__(NT, 9)
void quantum_layer_kernel(const float* __restrict__ x,
                          const float* __restrict__ weight,
                          float* __restrict__ out)
{
    __shared__ u64 sv[2][DIM];                 // 16 KB: per-warp statevector, 8B/amp
    __shared__ ulonglong2 RY[2][NLAYERS][NQ];  // (c dup, s dup)
    __shared__ u64 FE[2][NLAYERS][NQ][3];      // eps factors: FX, FYn, FYp
    __shared__ u64 FG[2][NLAYERS][NQ][3];      // gamma factors

    const int tid  = threadIdx.x;
    const int wp   = tid >> 5;
    const int lane = tid & 31;
    const int b    = blockIdx.x * 2 + wp;      // this warp's batch element
    u64* __restrict__ svw = sv[wp];

    // ---- per-wire ZYZ coefficients (single batch; lanes 0..9) ----
    if (lane < NQ) {
        const int w = lane;
        float ang = tanhf(x[b * NQ + w]) * PI_F;
        for (int l = 0; l < NLAYERS; ++l) {
            float th1 = weight[(l * NQ + w) * 3 + 0];
            float th2 = weight[(l * NQ + w) * 3 + 1];
            float th3 = weight[(l * NQ + w) * 3 + 2];
            float s0, c0, s1, c1, s2, c2, s3, c3;
            __sincosf(0.5f * ang, &s0, &c0);
            __sincosf(0.5f * th1, &s1, &c1);
            __sincosf(0.5f * th2, &s2, &c2);
            __sincosf(0.5f * th3, &s3, &c3);
            float2 d1m = make_float2(c1, -s1), d1p = make_float2(c1, s1);
            float2 d3m = make_float2(c3, -s3), d3p = make_float2(c3, s3);
            // u = m00, v = m10 of the fused SU(2) matrix
            float2 u = cmul(d3m, csub(cscale(c2 * c0, d1m), cscale(s2 * s0, d1p)));
            float2 vv = cmul(d3p, cadd(cscale(s2 * c0, d1m), cscale(c2 * s0, d1p)));
            float c = sqrtf(fmaf(u.x, u.x, u.y * u.y));
            float s = sqrtf(fmaf(vv.x, vv.x, vv.y * vv.y));
            float au = atan2f(u.y, u.x);
            float av = atan2f(vv.y, vv.x);
            float sg, cg, se, ce;
            __sincosf(av - au, &sg, &cg);    // e^{i*gamma}
            __sincosf(-av - au, &se, &ce);   // e^{i*eps}
            RY[wp][l][w] = make_ulonglong2(pk2(c, c), pk2(s, s));
            FE[wp][l][w][0] = pk2(ce, ce);
            FE[wp][l][w][1] = pk2(-se, se);
            FE[wp][l][w][2] = pk2(se, -se);
            FG[wp][l][w][0] = pk2(cg, cg);
            FG[wp][l][w][1] = pk2(-sg, sg);
            FG[wp][l][w][2] = pk2(sg, -sg);
        }
    }
    __syncwarp();

    // ---- state: 32 amps/thread, TWO arrangements per layer:
    //  A: j = (lane<<5)|r   reg bit b -> wire 9-b (wires 9..5); lane bit k -> wire 4-k
    //  B: j = (r<<5)|lane   reg bit b -> wire 4-b (wires 4..0); lane bit k -> wire 9-k
    u64 v[32];

    const int baseA = (lane << 5) | lane;          // phys32(lane<<5)
    const int baseB = lane;                        // phys32(lane)
    const int baseS = phys32(pinv10(lane));        // scatter lane base

    // ===== layer 0: closed-form product state directly in B arrangement =====
    {
        // amp((r<<5)|lane) = prod_{lane bit k} (set? s:c)[wire 9-k]
        //                  * prod_{reg  bit b} (set? s:c)[wire 4-b]
        float f = 1.0f;
        #pragma unroll
        for (int k = 0; k < 5; ++k) {
            ulonglong2 q = RY[wp][0][9 - k];
            float cv, d0, sv2, d1;
            upk2(q.x, cv, d0); upk2(q.y, sv2, d1);
            f *= ((lane >> k) & 1) ? sv2 : cv;
        }
        float g[32];
        g[0] = f;
        #pragma unroll
        for (int bb = 0; bb < 5; ++bb) {
            ulonglong2 q = RY[wp][0][4 - bb];
            float cv, d0, sv2, d1;
            upk2(q.x, cv, d0); upk2(q.y, sv2, d1);
            #pragma unroll
            for (int i = 0; i < 16; ++i) {
                if (i < (1 << bb)) {
                    g[i | (1 << bb)] = g[i] * sv2;
                    g[i] = g[i] * cv;
                }
            }
        }
        #pragma unroll
        for (int r = 0; r < 32; ++r) v[r] = pk2(g[r], 0.0f);
        APPLY_DIAG5(FG[wp][0], 9, 4);              // gamma(0) before CNOT ring
        #pragma unroll
        for (int r = 0; r < 32; ++r) svw[baseS ^ scOff(r)] = v[r];
        __syncwarp();
    }

    #pragma unroll 1
    for (int l = 1; l < NLAYERS; ++l) {
        // ===== arrangement A: eps diag, then RY wires 9..5
        #pragma unroll
        for (int r = 0; r < 32; ++r) v[r] = svw[baseA ^ r];
        APPLY_DIAG5(FE[wp][l], 4, 9);
        APPLY_RY5(RY[wp][l][9], 0);
        APPLY_RY5(RY[wp][l][8], 1);
        APPLY_RY5(RY[wp][l][7], 2);
        APPLY_RY5(RY[wp][l][6], 3);
        APPLY_RY5(RY[wp][l][5], 4);
        #pragma unroll
        for (int r = 0; r < 32; ++r) svw[baseA ^ r] = v[r];
        __syncwarp();
        // ===== load arrangement B
        #pragma unroll
        for (int r = 0; r < 32; ++r) v[r] = svw[offB(r) ^ baseB];
        __syncwarp();   // all B loads done before any scatter overwrite
        // ===== arrangement B: RY wires 4..0
        APPLY_RY5(RY[wp][l][4], 0);
        APPLY_RY5(RY[wp][l][3], 1);
        APPLY_RY5(RY[wp][l][2], 2);
        APPLY_RY5(RY[wp][l][1], 3);
        APPLY_RY5(RY[wp][l][0], 4);
        if (l < NLAYERS - 1) {
            APPLY_DIAG5(FG[wp][l], 9, 4);          // gamma before CNOT ring
            #pragma unroll
            for (int r = 0; r < 32; ++r) svw[baseS ^ scOff(r)] = v[r];
            __syncwarp();
        }
    }

    // ---- measurement in arrangement B: amp x = (r<<5)|lane.
    // Final CNOT ring folded into signs: sign_w(x) = parity(x & mask_{9-w}),
    // mask_k = bits k..9 (k<=8), mask_9 = 0x1FF.
    float pp[32];
    #pragma unroll
    for (int r = 0; r < 32; ++r) {
        float a, bb; upk2(mul2(v[r], v[r]), a, bb);
        pp[r] = a + bb;
    }
    // reg-part parity partial sums over reg bits (j bits 5..9):
    // needed masks mr in {31,30,28,24,15}.
    float e[16], o[16];
    #pragma unroll
    for (int i = 0; i < 16; ++i) { e[i] = pp[2*i] - pp[2*i+1]; o[i] = pp[2*i] + pp[2*i+1]; }
    float f1[8], g1[8], h[8];
    #pragma unroll
    for (int i = 0; i < 8; ++i) { f1[i] = e[2*i] - e[2*i+1]; g1[i] = o[2*i] - o[2*i+1];
                                  h[i]  = o[2*i] + o[2*i+1]; }
    float f2[4], g2[4], k2[4], m2[4];
    #pragma unroll
    for (int i = 0; i < 4; ++i) { f2[i] = f1[2*i] - f1[2*i+1]; g2[i] = g1[2*i] - g1[2*i+1];
                                  k2[i] = h[2*i]  - h[2*i+1];  m2[i] = h[2*i]  + h[2*i+1]; }
    float f3a = f2[0] - f2[1], f3b = f2[2] - f2[3];
    float g3a = g2[0] - g2[1], g3b = g2[2] - g2[3];
    float k3a = k2[0] - k2[1], k3b = k2[2] - k2[3];
    float m3a = m2[0] - m2[1], m3b = m2[2] - m2[3];
    const float P31 = f3a - f3b;   // reg bits 0..4 signed
    const float P15 = f3a + f3b;   // reg bits 0..3
    const float P30 = g3a - g3b;   // reg bits 1..4
    const float P28 = k3a - k3b;   // reg bits 2..4
    const float P24 = m3a - m3b;   // reg bits 3..4

    const unsigned fullmask = 0xffffffffu;
    #pragma unroll
    for (int k = 0; k < NQ; ++k) {
        float acc = (k <= 5) ? P31 : (k == 6) ? P30 : (k == 7) ? P28
                  : (k == 8) ? P24 : P15;
        const unsigned mt = (k == 0 || k == 9) ? 31u : (k == 1) ? 30u
                          : (k == 2) ? 28u : (k == 3) ? 24u : (k == 4) ? 16u : 0u;
        if (mt && (__popc((unsigned)lane & mt) & 1)) acc = -acc;
        #pragma unroll
        for (int off = 16; off; off >>= 1)
            acc += __shfl_xor_sync(fullmask, acc, off);
        if (lane == 0) out[b * NQ + (9 - k)] = acc;
    }
}

extern "C" void kernel_launch(void* const* d_in, const int* in_sizes, int n_in,
                              void* d_out, int out_size) {
    const float* x      = (const float*)d_in[0];   // (16384, 10) float32
    const float* weight = (const float*)d_in[1];   // (4, 10, 3)  float32
    float* out          = (float*)d_out;           // (16384, 10) float32
    const int batch  = in_sizes[0] / NQ;
    const int blocks = batch / 2;                  // 2 batch elems per block (1/warp)
    quantum_layer_kernel<<<blocks, NT>>>(x, weight, out);
}